// round 2
// baseline (speedup 1.0000x reference)
#include <cuda_runtime.h>
#include <cstddef>

// Eq1to3: out[n,s,i,j,k] = Yi[n,s,i] + Yj[n,s,j] + Yk[n,s,k] + S[n,s] + bias[s]
//   Y[n,s,b,m] = sum_d x[n,d,m] * coefs[d,s,b]   (b = 0,1,2)
//   S[n,s]     = sum_d (sum_t x[n,d,t]) * coefs[d,s,3]
//
// Shapes: x (4,16,96) f32, coefs (16,16,4) f32, bias (1,16,1,1,1) f32,
// out (4,16,96,96,96) f32 = 226.5 MB. Pure HBM-store bound.
//
// Grid: one block per (n,s,i) = 6144 blocks; each writes a 96x96 plane
// with float4 coalesced stores. All contractions recomputed per block
// (inputs tiny, L1/L2 resident).

#define M_DIM 96
#define D_DIM 16
#define S_DIM 16
#define PLANE (M_DIM * M_DIM)      // 9216 floats
#define PLANE4 (PLANE / 4)         // 2304 float4

__global__ __launch_bounds__(256, 8)
void eq1to3_kernel(const float* __restrict__ x,
                   const float* __restrict__ coefs,
                   const float* __restrict__ bias,
                   float* __restrict__ out) {
    const int bid = blockIdx.x;
    const int i = bid % M_DIM;
    const int s = (bid / M_DIM) % S_DIM;
    const int n = bid / (M_DIM * S_DIM);
    const int t = threadIdx.x;

    __shared__ float Yj[M_DIM];
    __shared__ float Yk[M_DIM];
    __shared__ float xs[D_DIM];

    const float* __restrict__ xn = x + (size_t)n * D_DIM * M_DIM;
    const float* __restrict__ cs = coefs + s * 4;   // c[d,s,b] at d*64 + s*4 + b

    if (t < M_DIM) {
        float yj = 0.f, yk = 0.f;
        #pragma unroll
        for (int d = 0; d < D_DIM; d++) {
            float xv = xn[d * M_DIM + t];
            yj = fmaf(xv, cs[d * 64 + 1], yj);
            yk = fmaf(xv, cs[d * 64 + 2], yk);
        }
        Yj[t] = yj;
        Yk[t] = yk;
    } else if (t < M_DIM + D_DIM) {
        const int d = t - M_DIM;
        const float* __restrict__ row = xn + d * M_DIM;
        float sum = 0.f;
        #pragma unroll 8
        for (int m = 0; m < M_DIM; m++) sum += row[m];
        xs[d] = sum;
    }
    __syncthreads();

    // Every thread folds the scalar part redundantly (32 FMAs).
    float base = bias[s];
    #pragma unroll
    for (int d = 0; d < D_DIM; d++) {
        base = fmaf(xn[d * M_DIM + i], cs[d * 64 + 0], base);
        base = fmaf(xs[d],             cs[d * 64 + 3], base);
    }

    float4* __restrict__ o4 =
        reinterpret_cast<float4*>(out + (size_t)bid * PLANE);

    // 2304 float4 per block, 9 per thread @ 256 threads. Coalesced STG.128.
    #pragma unroll
    for (int q = t; q < PLANE4; q += 256) {
        const int j  = q / (M_DIM / 4);
        const int k4 = (q % (M_DIM / 4)) * 4;
        const float bj = base + Yj[j];
        float4 v;
        v.x = bj + Yk[k4 + 0];
        v.y = bj + Yk[k4 + 1];
        v.z = bj + Yk[k4 + 2];
        v.w = bj + Yk[k4 + 3];
        o4[q] = v;
    }
}

extern "C" void kernel_launch(void* const* d_in, const int* in_sizes, int n_in,
                              void* d_out, int out_size) {
    const float* x     = (const float*)d_in[0];
    const float* coefs = (const float*)d_in[1];
    const float* bias  = (const float*)d_in[2];
    float* out = (float*)d_out;

    const int blocks = 4 * S_DIM * M_DIM;   // 6144
    eq1to3_kernel<<<blocks, 256>>>(x, coefs, bias, out);
}

// round 3
// speedup vs baseline: 1.0036x; 1.0036x over previous
#include <cuda_runtime.h>
#include <cstddef>

// Eq1to3: out[n,s,i,j,k] = Yi[n,s,i] + Yj[n,s,j] + Yk[n,s,k] + S[n,s] + bias[s]
//   Y[n,s,b,m] = sum_d x[n,d,m] * coefs[d,s,b]   (b = 0,1,2)
//   S[n,s]     = sum_d (sum_t x[n,d,t]) * coefs[d,s,3]
//
// Shapes: x (4,16,96) f32, coefs (16,16,4) f32, bias (1,16,1,1,1) f32,
// out (4,16,96,96,96) f32 = 226.5 MB. Pure HBM-store bound.
//
// Grid: one block per (n,s,i) = 6144 blocks; each writes a 96x96 plane
// with float4 coalesced stores. All contractions recomputed per block
// (inputs tiny, L1/L2 resident).

#define M_DIM 96
#define D_DIM 16
#define S_DIM 16
#define PLANE (M_DIM * M_DIM)      // 9216 floats
#define PLANE4 (PLANE / 4)         // 2304 float4

__global__ __launch_bounds__(256, 8)
void eq1to3_kernel(const float* __restrict__ x,
                   const float* __restrict__ coefs,
                   const float* __restrict__ bias,
                   float* __restrict__ out) {
    const int bid = blockIdx.x;
    const int i = bid % M_DIM;
    const int s = (bid / M_DIM) % S_DIM;
    const int n = bid / (M_DIM * S_DIM);
    const int t = threadIdx.x;

    __shared__ float Yj[M_DIM];
    __shared__ float Yk[M_DIM];
    __shared__ float xs[D_DIM];

    const float* __restrict__ xn = x + (size_t)n * D_DIM * M_DIM;
    const float* __restrict__ cs = coefs + s * 4;   // c[d,s,b] at d*64 + s*4 + b

    if (t < M_DIM) {
        float yj = 0.f, yk = 0.f;
        #pragma unroll
        for (int d = 0; d < D_DIM; d++) {
            float xv = xn[d * M_DIM + t];
            yj = fmaf(xv, cs[d * 64 + 1], yj);
            yk = fmaf(xv, cs[d * 64 + 2], yk);
        }
        Yj[t] = yj;
        Yk[t] = yk;
    } else if (t < M_DIM + D_DIM) {
        const int d = t - M_DIM;
        const float* __restrict__ row = xn + d * M_DIM;
        float sum = 0.f;
        #pragma unroll 8
        for (int m = 0; m < M_DIM; m++) sum += row[m];
        xs[d] = sum;
    }
    __syncthreads();

    // Every thread folds the scalar part redundantly (32 FMAs).
    float base = bias[s];
    #pragma unroll
    for (int d = 0; d < D_DIM; d++) {
        base = fmaf(xn[d * M_DIM + i], cs[d * 64 + 0], base);
        base = fmaf(xs[d],             cs[d * 64 + 3], base);
    }

    float4* __restrict__ o4 =
        reinterpret_cast<float4*>(out + (size_t)bid * PLANE);

    // 2304 float4 per block, 9 per thread @ 256 threads. Coalesced STG.128.
    #pragma unroll
    for (int q = t; q < PLANE4; q += 256) {
        const int j  = q / (M_DIM / 4);
        const int k4 = (q % (M_DIM / 4)) * 4;
        const float bj = base + Yj[j];
        float4 v;
        v.x = bj + Yk[k4 + 0];
        v.y = bj + Yk[k4 + 1];
        v.z = bj + Yk[k4 + 2];
        v.w = bj + Yk[k4 + 3];
        o4[q] = v;
    }
}

extern "C" void kernel_launch(void* const* d_in, const int* in_sizes, int n_in,
                              void* d_out, int out_size) {
    const float* x     = (const float*)d_in[0];
    const float* coefs = (const float*)d_in[1];
    const float* bias  = (const float*)d_in[2];
    float* out = (float*)d_out;

    const int blocks = 4 * S_DIM * M_DIM;   // 6144
    eq1to3_kernel<<<blocks, 256>>>(x, coefs, bias, out);
}

// round 4
// speedup vs baseline: 1.3329x; 1.3282x over previous
#include <cuda_runtime.h>
#include <cstddef>

// Eq1to3: out[n,s,i,j,k] = Yi[n,s,i] + Yj[n,s,j] + Yk[n,s,k] + S[n,s] + bias[s]
//
// Two-kernel split:
//   1) precompute_kernel: materialize YJ, YK, BASE (= bias + S + Yi) into
//      __device__ scratch. 64 blocks x 96 threads, trivial.
//   2) store_kernel: 6144 blocks x 192 threads. Per block ~13 warp-LDGs,
//      hot loop = 1 LDS broadcast + 4 FADD + 1 STG.128 per float4.
// This removes the ~650 warp-LDG/block recompute that saturated the L1/LSU
// pipe (82.6%) in the previous version.

#define M_DIM 96
#define D_DIM 16
#define S_DIM 16
#define N_DIM 4
#define PLANE (M_DIM * M_DIM)          // 9216 floats per (n,s,i) plane
#define NS (N_DIM * S_DIM)             // 64

__device__ float g_YJ[NS * M_DIM];
__device__ float g_YK[NS * M_DIM];
__device__ float g_BASE[NS * M_DIM];

// ---------------------------------------------------------------------------
// Kernel 1: per (n,s): Yb[m] = sum_d x[n,d,m] * c[d,s,b];
//           S = sum_d (sum_t x[n,d,t]) * c[d,s,3]  (= sum_t sum_d x*c3)
//           BASE[n,s,i] = bias[s] + S + Yi[i]
// ---------------------------------------------------------------------------
__global__ void precompute_kernel(const float* __restrict__ x,
                                  const float* __restrict__ coefs,
                                  const float* __restrict__ bias) {
    const int ns = blockIdx.x;          // n*S_DIM + s
    const int s  = ns % S_DIM;
    const int n  = ns / S_DIM;
    const int t  = threadIdx.x;         // 0..95

    const float* __restrict__ xn = x + (size_t)n * D_DIM * M_DIM;

    float yi = 0.f, yj = 0.f, yk = 0.f, yw = 0.f;
    #pragma unroll
    for (int d = 0; d < D_DIM; d++) {
        const float xv = xn[d * M_DIM + t];
        const float* __restrict__ c = coefs + d * S_DIM * 4 + s * 4;
        yi = fmaf(xv, c[0], yi);
        yj = fmaf(xv, c[1], yj);
        yk = fmaf(xv, c[2], yk);
        yw = fmaf(xv, c[3], yw);
    }

    const int idx = ns * M_DIM + t;
    g_YJ[idx] = yj;
    g_YK[idx] = yk;

    // Block-reduce yw over 96 threads (3 warps) -> S
    __shared__ float red[3];
    #pragma unroll
    for (int o = 16; o > 0; o >>= 1)
        yw += __shfl_down_sync(0xffffffffu, yw, o);
    if ((t & 31) == 0) red[t >> 5] = yw;
    __syncthreads();
    const float S = red[0] + red[1] + red[2];

    g_BASE[idx] = bias[s] + S + yi;
}

// ---------------------------------------------------------------------------
// Kernel 2: one block per (n,s,i) plane. 192 threads = 24 k-groups x 8 j-rows.
// Each thread keeps vk = base + Yk[k4..k4+3] in registers for all 12 passes.
// ---------------------------------------------------------------------------
__global__ __launch_bounds__(192)
void store_kernel(float* __restrict__ out) {
    const int bid = blockIdx.x;         // n*S*M + s*M + i
    const int i   = bid % M_DIM;
    const int ns  = bid / M_DIM;        // n*S + s
    const int t   = threadIdx.x;
    const int kg  = t % 24;             // k-group: k4 = kg*4
    const int jb  = t / 24;             // 0..7

    __shared__ float yjs[M_DIM];

    const float4* __restrict__ YJ4 =
        reinterpret_cast<const float4*>(g_YJ + ns * M_DIM);
    const float4* __restrict__ YK4 =
        reinterpret_cast<const float4*>(g_YK + ns * M_DIM);

    if (t < 24) reinterpret_cast<float4*>(yjs)[t] = YJ4[t];

    const float  base = g_BASE[ns * M_DIM + i];   // broadcast within warp
    const float4 yk4  = YK4[kg];
    float4 vk;
    vk.x = base + yk4.x;
    vk.y = base + yk4.y;
    vk.z = base + yk4.z;
    vk.w = base + yk4.w;

    __syncthreads();

    float4* __restrict__ o4 =
        reinterpret_cast<float4*>(out + (size_t)bid * PLANE);

    // 12 passes over j = jb + 8*p; each warp writes a contiguous 512B span.
    #pragma unroll
    for (int p = 0; p < 12; p++) {
        const int   j  = jb + 8 * p;
        const float yj = yjs[j];
        float4 v;
        v.x = vk.x + yj;
        v.y = vk.y + yj;
        v.z = vk.z + yj;
        v.w = vk.w + yj;
        o4[j * 24 + kg] = v;
    }
}

extern "C" void kernel_launch(void* const* d_in, const int* in_sizes, int n_in,
                              void* d_out, int out_size) {
    const float* x     = (const float*)d_in[0];
    const float* coefs = (const float*)d_in[1];
    const float* bias  = (const float*)d_in[2];
    float* out = (float*)d_out;

    precompute_kernel<<<NS, M_DIM>>>(x, coefs, bias);
    store_kernel<<<N_DIM * S_DIM * M_DIM, 192>>>(out);
}

// round 5
// speedup vs baseline: 1.9133x; 1.4354x over previous
#include <cuda_runtime.h>
#include <cstddef>

// Eq1to3: out[n,s,i,j,k] = Yi[n,s,i] + Yj[n,s,j] + Yk[n,s,k] + S[n,s] + bias[s]
//
// Two-kernel split:
//   1) precompute_kernel: materialize YJ, YK, BASE (= bias + S + Yi).
//   2) store_kernel: 6144 blocks x 192 threads. All Yj/Yk values hoisted
//      into REGISTERS before the store loop; steady state is pure
//      FADD + STG.128 (streaming hint), no shared-memory traffic.

#define M_DIM 96
#define D_DIM 16
#define S_DIM 16
#define N_DIM 4
#define PLANE (M_DIM * M_DIM)          // 9216 floats per (n,s,i) plane
#define NS (N_DIM * S_DIM)             // 64

__device__ float g_YJ[NS * M_DIM];
__device__ float g_YK[NS * M_DIM];
__device__ float g_BASE[NS * M_DIM];

// ---------------------------------------------------------------------------
// Kernel 1: per (n,s): Yb[m] = sum_d x[n,d,m] * c[d,s,b];
//           S = sum_d (sum_t x[n,d,t]) * c[d,s,3]
//           BASE[n,s,i] = bias[s] + S + Yi[i]
// ---------------------------------------------------------------------------
__global__ void precompute_kernel(const float* __restrict__ x,
                                  const float* __restrict__ coefs,
                                  const float* __restrict__ bias) {
    const int ns = blockIdx.x;          // n*S_DIM + s
    const int s  = ns % S_DIM;
    const int n  = ns / S_DIM;
    const int t  = threadIdx.x;         // 0..95

    const float* __restrict__ xn = x + (size_t)n * D_DIM * M_DIM;

    float yi = 0.f, yj = 0.f, yk = 0.f, yw = 0.f;
    #pragma unroll
    for (int d = 0; d < D_DIM; d++) {
        const float xv = xn[d * M_DIM + t];
        const float* __restrict__ c = coefs + d * S_DIM * 4 + s * 4;
        yi = fmaf(xv, c[0], yi);
        yj = fmaf(xv, c[1], yj);
        yk = fmaf(xv, c[2], yk);
        yw = fmaf(xv, c[3], yw);
    }

    const int idx = ns * M_DIM + t;
    g_YJ[idx] = yj;
    g_YK[idx] = yk;

    // Block-reduce yw over 96 threads (3 warps) -> S
    __shared__ float red[3];
    #pragma unroll
    for (int o = 16; o > 0; o >>= 1)
        yw += __shfl_down_sync(0xffffffffu, yw, o);
    if ((t & 31) == 0) red[t >> 5] = yw;
    __syncthreads();
    const float S = red[0] + red[1] + red[2];

    g_BASE[idx] = bias[s] + S + yi;
}

// ---------------------------------------------------------------------------
// Kernel 2: one block per (n,s,i) plane. 192 threads = 24 k-groups x 8 j-rows.
// Thread keeps vk = base + Yk[k4..k4+3] AND all 12 of its yj values in
// registers; the store loop has no memory reads at all.
// ---------------------------------------------------------------------------
__global__ __launch_bounds__(192)
void store_kernel(float* __restrict__ out) {
    const int bid = blockIdx.x;         // n*S*M + s*M + i
    const int i   = bid % M_DIM;
    const int ns  = bid / M_DIM;        // n*S + s
    const int t   = threadIdx.x;
    const int kg  = t % 24;             // k-group: k4 = kg*4
    const int jb  = t / 24;             // 0..7

    __shared__ float yjs[M_DIM];

    const float4* __restrict__ YJ4 =
        reinterpret_cast<const float4*>(g_YJ + ns * M_DIM);
    const float4* __restrict__ YK4 =
        reinterpret_cast<const float4*>(g_YK + ns * M_DIM);

    if (t < 24) reinterpret_cast<float4*>(yjs)[t] = YJ4[t];

    const float  base = g_BASE[ns * M_DIM + i];   // warp-broadcast LDG
    const float4 yk4  = YK4[kg];
    float4 vk;
    vk.x = base + yk4.x;
    vk.y = base + yk4.y;
    vk.z = base + yk4.z;
    vk.w = base + yk4.w;

    __syncthreads();

    // Hoist this thread's 12 yj values into registers (batched LDS, full MLP).
    float yj[12];
    #pragma unroll
    for (int p = 0; p < 12; p++) yj[p] = yjs[jb + 8 * p];

    float4* __restrict__ o4 =
        reinterpret_cast<float4*>(out + (size_t)bid * PLANE);

    // Pure compute+store loop: 4 FADD + 1 STG.128 (streaming) per iteration.
    #pragma unroll
    for (int p = 0; p < 12; p++) {
        const int j = jb + 8 * p;
        float4 v;
        v.x = vk.x + yj[p];
        v.y = vk.y + yj[p];
        v.z = vk.z + yj[p];
        v.w = vk.w + yj[p];
        __stcs(&o4[j * 24 + kg], v);
    }
}

extern "C" void kernel_launch(void* const* d_in, const int* in_sizes, int n_in,
                              void* d_out, int out_size) {
    const float* x     = (const float*)d_in[0];
    const float* coefs = (const float*)d_in[1];
    const float* bias  = (const float*)d_in[2];
    float* out = (float*)d_out;

    precompute_kernel<<<NS, M_DIM>>>(x, coefs, bias);
    store_kernel<<<N_DIM * S_DIM * M_DIM, 192>>>(out);
}

// round 6
// speedup vs baseline: 1.9149x; 1.0009x over previous
#include <cuda_runtime.h>
#include <cstddef>

// Eq1to3: out[n,s,i,j,k] = Yi[n,s,i] + Yj[n,s,j] + Yk[n,s,k] + S[n,s] + bias[s]
//
// Two-kernel split with PDL overlap:
//   1) precompute_kernel: materialize YJ, YK, BASE (= bias + S + Yi).
//   2) store_kernel: launched with programmatic stream serialization so its
//      prologue overlaps kernel 1; blocks wait at cudaGridDependencySynchronize()
//      before touching the scratch arrays. Store loop is read-free:
//      4 FADD + 1 STG.128 (streaming) per float4.

#define M_DIM 96
#define D_DIM 16
#define S_DIM 16
#define N_DIM 4
#define PLANE (M_DIM * M_DIM)          // 9216 floats per (n,s,i) plane
#define NS (N_DIM * S_DIM)             // 64

__device__ float g_YJ[NS * M_DIM];
__device__ float g_YK[NS * M_DIM];
__device__ float g_BASE[NS * M_DIM];

// ---------------------------------------------------------------------------
// Kernel 1: per (n,s): Yb[m] = sum_d x[n,d,m] * c[d,s,b];
//           S = sum_d (sum_t x[n,d,t]) * c[d,s,3]
//           BASE[n,s,i] = bias[s] + S + Yi[i]
// ---------------------------------------------------------------------------
__global__ void precompute_kernel(const float* __restrict__ x,
                                  const float* __restrict__ coefs,
                                  const float* __restrict__ bias) {
    const int ns = blockIdx.x;          // n*S_DIM + s
    const int s  = ns % S_DIM;
    const int n  = ns / S_DIM;
    const int t  = threadIdx.x;         // 0..95

    const float* __restrict__ xn = x + (size_t)n * D_DIM * M_DIM;

    float yi = 0.f, yj = 0.f, yk = 0.f, yw = 0.f;
    #pragma unroll
    for (int d = 0; d < D_DIM; d++) {
        const float xv = xn[d * M_DIM + t];
        const float* __restrict__ c = coefs + d * S_DIM * 4 + s * 4;
        yi = fmaf(xv, c[0], yi);
        yj = fmaf(xv, c[1], yj);
        yk = fmaf(xv, c[2], yk);
        yw = fmaf(xv, c[3], yw);
    }

    const int idx = ns * M_DIM + t;
    g_YJ[idx] = yj;
    g_YK[idx] = yk;

    // Block-reduce yw over 96 threads (3 warps) -> S
    __shared__ float red[3];
    #pragma unroll
    for (int o = 16; o > 0; o >>= 1)
        yw += __shfl_down_sync(0xffffffffu, yw, o);
    if ((t & 31) == 0) red[t >> 5] = yw;
    __syncthreads();
    const float S = red[0] + red[1] + red[2];

    g_BASE[idx] = bias[s] + S + yi;
}

// ---------------------------------------------------------------------------
// Kernel 2: one block per (n,s,i) plane. 192 threads = 24 k-groups x 8 j-rows.
// Prologue (index/address math) runs BEFORE the grid-dependency sync so it
// overlaps kernel 1 under PDL.
// ---------------------------------------------------------------------------
__global__ __launch_bounds__(192)
void store_kernel(float* __restrict__ out) {
    const int bid = blockIdx.x;         // n*S*M + s*M + i
    const int i   = bid % M_DIM;
    const int ns  = bid / M_DIM;        // n*S + s
    const int t   = threadIdx.x;
    const int kg  = t % 24;             // k-group: k4 = kg*4
    const int jb  = t / 24;             // 0..7

    float4* __restrict__ o4 =
        reinterpret_cast<float4*>(out + (size_t)bid * PLANE);

    __shared__ float yjs[M_DIM];

    // Wait for precompute_kernel's writes to be visible.
    cudaGridDependencySynchronize();

    const float4* __restrict__ YJ4 =
        reinterpret_cast<const float4*>(g_YJ + ns * M_DIM);
    const float4* __restrict__ YK4 =
        reinterpret_cast<const float4*>(g_YK + ns * M_DIM);

    if (t < 24) reinterpret_cast<float4*>(yjs)[t] = YJ4[t];

    const float  base = g_BASE[ns * M_DIM + i];   // warp-broadcast LDG
    const float4 yk4  = YK4[kg];
    float4 vk;
    vk.x = base + yk4.x;
    vk.y = base + yk4.y;
    vk.z = base + yk4.z;
    vk.w = base + yk4.w;

    __syncthreads();

    // Hoist this thread's 12 yj values into registers (batched LDS, full MLP).
    float yj[12];
    #pragma unroll
    for (int p = 0; p < 12; p++) yj[p] = yjs[jb + 8 * p];

    // Pure compute+store loop: 4 FADD + 1 STG.128 (streaming) per iteration.
    // Each warp writes a contiguous 512B span per iteration.
    #pragma unroll
    for (int p = 0; p < 12; p++) {
        const int j = jb + 8 * p;
        float4 v;
        v.x = vk.x + yj[p];
        v.y = vk.y + yj[p];
        v.z = vk.z + yj[p];
        v.w = vk.w + yj[p];
        __stcs(&o4[j * 24 + kg], v);
    }
}

extern "C" void kernel_launch(void* const* d_in, const int* in_sizes, int n_in,
                              void* d_out, int out_size) {
    const float* x     = (const float*)d_in[0];
    const float* coefs = (const float*)d_in[1];
    const float* bias  = (const float*)d_in[2];
    float* out = (float*)d_out;

    precompute_kernel<<<NS, M_DIM>>>(x, coefs, bias);

    // Launch store_kernel with programmatic dependent launch so its prologue
    // overlaps precompute_kernel; the grid waits at
    // cudaGridDependencySynchronize() before reading the scratch arrays.
    cudaLaunchConfig_t cfg = {};
    cfg.gridDim  = dim3(N_DIM * S_DIM * M_DIM);
    cfg.blockDim = dim3(192);
    cfg.dynamicSmemBytes = 0;
    cfg.stream = 0;
    cudaLaunchAttribute attrs[1];
    attrs[0].id = cudaLaunchAttributeProgrammaticStreamSerialization;
    attrs[0].val.programmaticStreamSerializationAllowed = 1;
    cfg.attrs = attrs;
    cfg.numAttrs = 1;
    cudaLaunchKernelEx(&cfg, store_kernel, out);
}